// round 4
// baseline (speedup 1.0000x reference)
#include <cuda_runtime.h>

// FlowGradientReg: bilinear warp, smem tile channel-interleaved as float4.
// x:[B,C,H,W] f32, flow:[B,H,W,2] f32 -> out:[B,C,H,W] f32
// B=32, C=3, H=512, W=512

constexpr int B = 32, C = 3, H = 512, W = 512;
constexpr int HW = H * W;

constexpr int TSH = 64, TSW = 32;          // output tile per block
constexpr int HALO = 16;
constexpr int SH  = TSH + 2 * HALO;        // 96 covered rows
constexpr int SWD = TSW + 2 * HALO;        // 64 covered cols
constexpr int SP4 = SWD + 1;               // 65 float4 row stride (odd -> bank spread)
constexpr int SMEM_BYTES = SH * SP4 * 16;  // 99840

constexpr int THREADS = 512;
constexpr int TILES_X = W / TSW;           // 16
constexpr int TILES_Y = H / TSH;           // 8
constexpr int TILES_PER_IMG = TILES_X * TILES_Y;  // 128

__global__ void __launch_bounds__(THREADS) flow_warp_v4_kernel(
    const float* __restrict__ x,
    const float* __restrict__ flow,
    float* __restrict__ out)
{
    extern __shared__ float4 sm4[];        // [SH][SP4], (c0,c1,c2,pad)

    int tid = threadIdx.x;
    int bx  = blockIdx.x;
    int b   = bx >> 7;                     // / TILES_PER_IMG
    int t   = bx & 127;
    int ti0 = (t >> 4) * TSH;
    int tj0 = (t & 15) * TSW;

    const float* xb = x + (size_t)b * C * HW;

    // ---- Phase 1: load covered region, channel-interleave into smem ----
    // covered rows [ti0-16, ti0+80), cols [tj0-16, tj0+48)
    #pragma unroll 1
    for (int it = tid; it < SH * SWD; it += THREADS) {
        int r  = it >> 6;                  // / SWD
        int c  = it & 63;
        int gr = ti0 - HALO + r;
        int gc = tj0 - HALO + c;
        if ((unsigned)gr < (unsigned)H && (unsigned)gc < (unsigned)W) {
            int g = gr * W + gc;
            float4 v;
            v.x = __ldg(xb + g);
            v.y = __ldg(xb + HW + g);
            v.z = __ldg(xb + 2 * HW + g);
            v.w = 0.0f;
            sm4[r * SP4 + c] = v;
        }
    }
    __syncthreads();

    // ---- Phase 2: bilinear gather, 4x LDS.128 per pixel ----
    #pragma unroll 1
    for (int k = 0; k < (TSH * TSW) / THREADS; k++) {
        int px  = tid + k * THREADS;
        int row = px >> 5;                 // / TSW
        int col = px & 31;
        int gi  = ti0 + row;
        int gj  = tj0 + col;
        int p   = gi * W + gj;

        float2 f = reinterpret_cast<const float2*>(flow)[(size_t)b * HW + p];

        float gx = fmaf((float)gj, 2.0f / (float)(W - 1), -1.0f) + f.x;
        float gy = fmaf((float)gi, 2.0f / (float)(H - 1), -1.0f) + f.y;
        float jc = (float)(W - 1) * (gx + 1.0f) * 0.5f;
        float ic = (float)(H - 1) * (gy + 1.0f) * 0.5f;

        float i1f = fminf(fmaxf(floorf(ic), 0.0f), (float)(H - 1));
        float i2f = fminf(i1f + 1.0f, (float)(H - 1));
        float j1f = fminf(fmaxf(floorf(jc), 0.0f), (float)(W - 1));
        float j2f = fminf(j1f + 1.0f, (float)(W - 1));

        int i1 = (int)i1f, i2 = (int)i2f, j1 = (int)j1f, j2 = (int)j2f;
        float di = ic - i1f;
        float dj = jc - j1f;

        float4 v11, v12, v21, v22;

        bool in_tile = (i1 >= ti0 - HALO) && (i2 <= ti0 + TSH + HALO - 1) &&
                       (j1 >= tj0 - HALO) && (j2 <= tj0 + TSW + HALO - 1);

        if (in_tile) {
            int sr1 = i1 - (ti0 - HALO);
            int sr2 = i2 - (ti0 - HALO);
            int sc1 = j1 - (tj0 - HALO);
            int sc2 = j2 - (tj0 - HALO);
            v11 = sm4[sr1 * SP4 + sc1];
            v12 = sm4[sr1 * SP4 + sc2];
            v21 = sm4[sr2 * SP4 + sc1];
            v22 = sm4[sr2 * SP4 + sc2];
        } else {
            int r1 = i1 * W, r2 = i2 * W;
            v11 = make_float4(__ldg(xb + r1 + j1), __ldg(xb + HW + r1 + j1),
                              __ldg(xb + 2 * HW + r1 + j1), 0.f);
            v12 = make_float4(__ldg(xb + r1 + j2), __ldg(xb + HW + r1 + j2),
                              __ldg(xb + 2 * HW + r1 + j2), 0.f);
            v21 = make_float4(__ldg(xb + r2 + j1), __ldg(xb + HW + r2 + j1),
                              __ldg(xb + 2 * HW + r2 + j1), 0.f);
            v22 = make_float4(__ldg(xb + r2 + j2), __ldg(xb + HW + r2 + j2),
                              __ldg(xb + 2 * HW + r2 + j2), 0.f);
        }

        float* ob = out + (size_t)b * C * HW + p;

        float qa, qb;
        qa = fmaf(di, v21.x - v11.x, v11.x);
        qb = fmaf(di, v22.x - v12.x, v12.x);
        ob[0] = fmaf(dj, qb - qa, qa);
        qa = fmaf(di, v21.y - v11.y, v11.y);
        qb = fmaf(di, v22.y - v12.y, v12.y);
        ob[HW] = fmaf(dj, qb - qa, qa);
        qa = fmaf(di, v21.z - v11.z, v11.z);
        qb = fmaf(di, v22.z - v12.z, v12.z);
        ob[2 * HW] = fmaf(dj, qb - qa, qa);
    }
}

extern "C" void kernel_launch(void* const* d_in, const int* in_sizes, int n_in,
                              void* d_out, int out_size)
{
    const float* x    = (const float*)d_in[0];
    const float* flow = (const float*)d_in[1];
    float* out        = (float*)d_out;

    static bool configured = false;
    if (!configured) {
        cudaFuncSetAttribute(flow_warp_v4_kernel,
                             cudaFuncAttributeMaxDynamicSharedMemorySize, SMEM_BYTES);
        configured = true;
    }

    int blocks = B * TILES_PER_IMG;        // 4096
    flow_warp_v4_kernel<<<blocks, THREADS, SMEM_BYTES>>>(x, flow, out);
}

// round 7
// speedup vs baseline: 1.5332x; 1.5332x over previous
#include <cuda_runtime.h>

// FlowGradientReg: bilinear warp via smem-tiled gather, max-occupancy variant.
// x:[B,C,H,W] f32, flow:[B,H,W,2] f32 -> out:[B,C,H,W] f32
// B=32, C=3, H=512, W=512

constexpr int B = 32, C = 3, H = 512, W = 512;
constexpr int HW = H * W;

constexpr int TSH = 64, TSW = 64;       // tile (output pixels per block)
constexpr int HALO = 16;
constexpr int SH = TSH + 2 * HALO;      // 96 rows covered in smem
constexpr int SWD = TSW + 2 * HALO;     // 96 cols covered
constexpr int SP = SWD + 1;             // 97: row stride (97 mod 32 = 1)
constexpr int SMEM_FLOATS = C * SH * SP;            // 27936
constexpr int SMEM_BYTES = SMEM_FLOATS * 4;         // 111744

constexpr int THREADS = 1024;
constexpr int TILES_X = W / TSW;        // 8
constexpr int TILES_Y = H / TSH;        // 8
constexpr int TILES_PER_IMG = TILES_X * TILES_Y;    // 64
constexpr int NCOL4 = SWD / 4;          // 24 float4 per covered row

__global__ void __launch_bounds__(THREADS, 2) flow_warp_tile_kernel(
    const float* __restrict__ x,
    const float* __restrict__ flow,
    float* __restrict__ out)
{
    extern __shared__ float smem[];   // [C][SH][SP]

    int tid = threadIdx.x;
    int bx  = blockIdx.x;
    int b   = bx >> 6;                 // / TILES_PER_IMG
    int t   = bx & 63;
    int ti0 = (t >> 3) * TSH;
    int tj0 = (t & 7) * TSW;

    const float* xb = x + (size_t)b * C * HW;

    // ---- Phase 1: coalesced load of halo region into smem (float4) ----
    // covered global rows [ti0-16, ti0+80), cols [tj0-16, tj0+80), clipped
    #pragma unroll 1
    for (int it = tid; it < C * SH * NCOL4; it += THREADS) {
        int c   = it / (SH * NCOL4);
        int rem = it - c * (SH * NCOL4);
        int r   = rem / NCOL4;
        int q   = rem - r * NCOL4;
        int gr  = ti0 - HALO + r;
        int gc  = tj0 - HALO + 4 * q;
        if ((unsigned)gr < (unsigned)H && (unsigned)gc < (unsigned)W) {
            float4 v = *reinterpret_cast<const float4*>(xb + c * HW + gr * W + gc);
            float* s = smem + (c * SH + r) * SP + (gc - (tj0 - HALO));
            s[0] = v.x; s[1] = v.y; s[2] = v.z; s[3] = v.w;
        }
    }
    __syncthreads();

    // ---- Phase 2: per-pixel bilinear gather from smem ----
    #pragma unroll 1
    for (int k = 0; k < (TSH * TSW) / THREADS; k++) {
        int px  = tid + k * THREADS;
        int row = px >> 6;             // / TSW
        int col = px & 63;
        int gi  = ti0 + row;
        int gj  = tj0 + col;
        int p   = gi * W + gj;

        float2 f = reinterpret_cast<const float2*>(flow)[(size_t)b * HW + p];

        float gx = fmaf((float)gj, 2.0f / (float)(W - 1), -1.0f) + f.x;
        float gy = fmaf((float)gi, 2.0f / (float)(H - 1), -1.0f) + f.y;
        float jc = (float)(W - 1) * (gx + 1.0f) * 0.5f;
        float ic = (float)(H - 1) * (gy + 1.0f) * 0.5f;

        float i1f = fminf(fmaxf(floorf(ic), 0.0f), (float)(H - 1));
        float i2f = fminf(i1f + 1.0f, (float)(H - 1));
        float j1f = fminf(fmaxf(floorf(jc), 0.0f), (float)(W - 1));
        float j2f = fminf(j1f + 1.0f, (float)(W - 1));

        int i1 = (int)i1f, i2 = (int)i2f, j1 = (int)j1f, j2 = (int)j2f;
        float di = ic - i1f;
        float dj = jc - j1f;

        float q11[C], q12[C], q21[C], q22[C];

        bool in_tile = (i1 >= ti0 - HALO) && (i2 <= ti0 + TSH + HALO - 1) &&
                       (j1 >= tj0 - HALO) && (j2 <= tj0 + TSW + HALO - 1);

        if (in_tile) {
            int sr1 = i1 - (ti0 - HALO);
            int sr2 = i2 - (ti0 - HALO);
            int sc1 = j1 - (tj0 - HALO);
            int sc2 = j2 - (tj0 - HALO);
            #pragma unroll
            for (int c = 0; c < C; c++) {
                const float* sb = smem + c * SH * SP;
                q11[c] = sb[sr1 * SP + sc1];
                q12[c] = sb[sr1 * SP + sc2];
                q21[c] = sb[sr2 * SP + sc1];
                q22[c] = sb[sr2 * SP + sc2];
            }
        } else {
            int r1 = i1 * W, r2 = i2 * W;
            #pragma unroll
            for (int c = 0; c < C; c++) {
                const float* xc = xb + c * HW;
                q11[c] = __ldg(xc + r1 + j1);
                q12[c] = __ldg(xc + r1 + j2);
                q21[c] = __ldg(xc + r2 + j1);
                q22[c] = __ldg(xc + r2 + j2);
            }
        }

        float* ob = out + (size_t)b * C * HW + p;
        #pragma unroll
        for (int c = 0; c < C; c++) {
            float qa = fmaf(di, q21[c] - q11[c], q11[c]);
            float qb = fmaf(di, q22[c] - q12[c], q12[c]);
            ob[c * HW] = fmaf(dj, qb - qa, qa);
        }
    }
}

extern "C" void kernel_launch(void* const* d_in, const int* in_sizes, int n_in,
                              void* d_out, int out_size)
{
    const float* x    = (const float*)d_in[0];
    const float* flow = (const float*)d_in[1];
    float* out        = (float*)d_out;

    static bool configured = false;
    if (!configured) {
        cudaFuncSetAttribute(flow_warp_tile_kernel,
                             cudaFuncAttributeMaxDynamicSharedMemorySize, SMEM_BYTES);
        configured = true;
    }

    int blocks = B * TILES_PER_IMG;    // 2048
    flow_warp_tile_kernel<<<blocks, THREADS, SMEM_BYTES>>>(x, flow, out);
}